// round 2
// baseline (speedup 1.0000x reference)
#include <cuda_runtime.h>
#include <cuda_bf16.h>

// Problem constants
#define BATCH   8
#define SEQ     4096
#define DMODEL  1024
#define MTOT    (BATCH * SEQ)      // 32768
#define KTOT    DMODEL             // 1024
#define NTOT    (2 * DMODEL)       // 2048 fused output channels (decay | input)

// GEMM tiling
#define BM 128
#define BN 64
#define BK 16
#define TM 8
#define TN 4
#define NTHREADS 256

// Scratch for intermediates (decays after sigmoid, injections). 2 x 128 MB.
__device__ float g_decays[(size_t)MTOT * DMODEL];
__device__ float g_inj[(size_t)MTOT * DMODEL];

__device__ __forceinline__ float sigmoidf_fast(float x) {
    return 1.0f / (1.0f + __expf(-x));
}

// C[m, n] = sum_k X[m,k] * W[n,k]  (+bias, +sigmoid for decay half)
// n < 1024 -> W_decay row n, bias b_decay, sigmoid, write g_decays
// n >= 1024 -> W_input row n-1024, bias b_input, write g_inj
__global__ __launch_bounds__(NTHREADS)
void gemm_gate_kernel(const float* __restrict__ X,
                      const float* __restrict__ Wd,
                      const float* __restrict__ bd,
                      const float* __restrict__ Wi,
                      const float* __restrict__ bi) {
    __shared__ float As[BK][BM];   // [k][m]
    __shared__ float Bs[BK][BN];   // [k][n]

    const int tid = threadIdx.x;
    const int m0 = blockIdx.y * BM;
    const int n0 = blockIdx.x * BN;

    // BN=64 divides the 1024 boundary, so a CTA is entirely decay or input.
    const bool is_decay = (n0 < DMODEL);
    const float* __restrict__ W  = is_decay ? Wd : Wi;
    const float* __restrict__ bv = is_decay ? bd : bi;
    const int ncol0 = is_decay ? n0 : (n0 - DMODEL);

    const int tm0 = (tid >> 4) * TM;   // 0..120 step 8
    const int tn0 = (tid & 15) * TN;   // 0..60  step 4

    float acc[TM][TN];
#pragma unroll
    for (int i = 0; i < TM; ++i)
#pragma unroll
        for (int j = 0; j < TN; ++j) acc[i][j] = 0.0f;

    for (int k0 = 0; k0 < KTOT; k0 += BK) {
        // --- load X tile: 128 rows x 16 k = 512 float4, 2 per thread ---
#pragma unroll
        for (int r = 0; r < 2; ++r) {
            int idx4 = tid + r * NTHREADS;      // 0..511
            int m = idx4 >> 2;                  // 4 float4 per row
            int k = (idx4 & 3) * 4;
            float4 v = *reinterpret_cast<const float4*>(
                X + (size_t)(m0 + m) * KTOT + k0 + k);
            As[k + 0][m] = v.x;
            As[k + 1][m] = v.y;
            As[k + 2][m] = v.z;
            As[k + 3][m] = v.w;
        }
        // --- load W tile: 64 rows x 16 k = 256 float4, 1 per thread ---
        {
            int e = tid >> 2;
            int k = (tid & 3) * 4;
            float4 v = *reinterpret_cast<const float4*>(
                W + (size_t)(ncol0 + e) * KTOT + k0 + k);
            Bs[k + 0][e] = v.x;
            Bs[k + 1][e] = v.y;
            Bs[k + 2][e] = v.z;
            Bs[k + 3][e] = v.w;
        }
        __syncthreads();

#pragma unroll
        for (int k = 0; k < BK; ++k) {
            float4 a0 = *reinterpret_cast<const float4*>(&As[k][tm0]);
            float4 a1 = *reinterpret_cast<const float4*>(&As[k][tm0 + 4]);
            float4 bb = *reinterpret_cast<const float4*>(&Bs[k][tn0]);
            float a[TM] = {a0.x, a0.y, a0.z, a0.w, a1.x, a1.y, a1.z, a1.w};
            float bfr[TN] = {bb.x, bb.y, bb.z, bb.w};
#pragma unroll
            for (int i = 0; i < TM; ++i)
#pragma unroll
                for (int j = 0; j < TN; ++j)
                    acc[i][j] = fmaf(a[i], bfr[j], acc[i][j]);
        }
        __syncthreads();
    }

    // --- epilogue: bias (+ sigmoid), write scratch ---
    float4 bias4 = *reinterpret_cast<const float4*>(bv + ncol0 + tn0);
    float bias[TN] = {bias4.x, bias4.y, bias4.z, bias4.w};

    float* __restrict__ dst = is_decay ? g_decays : g_inj;
#pragma unroll
    for (int i = 0; i < TM; ++i) {
        int m = m0 + tm0 + i;
        float4 o;
        if (is_decay) {
            o.x = sigmoidf_fast(acc[i][0] + bias[0]);
            o.y = sigmoidf_fast(acc[i][1] + bias[1]);
            o.z = sigmoidf_fast(acc[i][2] + bias[2]);
            o.w = sigmoidf_fast(acc[i][3] + bias[3]);
        } else {
            o.x = acc[i][0] + bias[0];
            o.y = acc[i][1] + bias[1];
            o.z = acc[i][2] + bias[2];
            o.w = acc[i][3] + bias[3];
        }
        *reinterpret_cast<float4*>(dst + (size_t)m * DMODEL + ncol0 + tn0) = o;
    }
}

// One thread per (b, e) channel: sequential scan over T with unroll-8 prefetch.
__global__ __launch_bounds__(256)
void scan_kernel(float* __restrict__ out) {
    const int gid = blockIdx.x * blockDim.x + threadIdx.x;   // 0..8191
    const int b = gid >> 10;
    const int e = gid & (DMODEL - 1);
    size_t base = (size_t)b * SEQ * DMODEL + e;

    float s = 0.0f;
    for (int t = 0; t < SEQ; t += 8) {
        float d[8], v[8];
        size_t p = base + (size_t)t * DMODEL;
#pragma unroll
        for (int j = 0; j < 8; ++j) {
            d[j] = g_decays[p + (size_t)j * DMODEL];
            v[j] = g_inj[p + (size_t)j * DMODEL];
        }
#pragma unroll
        for (int j = 0; j < 8; ++j) {
            s = fmaf(d[j], s, v[j]);
            out[p + (size_t)j * DMODEL] = s;
        }
    }
}

extern "C" void kernel_launch(void* const* d_in, const int* in_sizes, int n_in,
                              void* d_out, int out_size) {
    const float* x_seq   = (const float*)d_in[0];  // [B, T, D]
    const float* W_decay = (const float*)d_in[1];  // [D, D]
    const float* b_decay = (const float*)d_in[2];  // [D]
    const float* W_input = (const float*)d_in[3];  // [D, D]
    const float* b_input = (const float*)d_in[4];  // [D]
    float* out = (float*)d_out;                    // [B, T, D]

    dim3 grid(NTOT / BN, MTOT / BM);               // (32, 256)
    gemm_gate_kernel<<<grid, NTHREADS>>>(x_seq, W_decay, b_decay, W_input, b_input);

    scan_kernel<<<(BATCH * DMODEL) / 256, 256>>>(out);
}

// round 4
// speedup vs baseline: 2.4531x; 2.4531x over previous
#include <cuda_runtime.h>
#include <cuda_bf16.h>
#include <cstdint>

// ---------------- problem constants ----------------
#define BATCH   8
#define SEQ     4096
#define DMODEL  1024
#define MTOT    (BATCH * SEQ)      // 32768
#define KTOT    DMODEL             // 1024
#define NTOT    (2 * DMODEL)       // 2048 fused (decay | input)

// ---------------- GEMM tiling ----------------
#define M_TILE   128
#define N_TILE   128
#define K_CHUNK  32
#define N_CHUNKS (KTOT / K_CHUNK)   // 32
#define GTHREADS 256

// smem: padded pitch 40 bf16 (80 B) -> conflict-free ldmatrix
#define PITCH 40
#define TILE_BYTES (128 * PITCH * 2)      // 10240
#define OFF_A_HI 0
#define OFF_A_LO (1 * TILE_BYTES)
#define OFF_B_HI (2 * TILE_BYTES)
#define OFF_B_LO (3 * TILE_BYTES)
#define STAGE_BYTES (4 * TILE_BYTES)      // 40960
#define SMEM_TOTAL  (2 * STAGE_BYTES)     // 81920

// ---------------- scan segmentation ----------------
#define NSEG   16
#define SEGLEN (SEQ / NSEG)         // 256

// ---------------- device scratch ----------------
__device__ __nv_bfloat16 X_hi[(size_t)MTOT * KTOT];
__device__ __nv_bfloat16 X_lo[(size_t)MTOT * KTOT];
__device__ __nv_bfloat16 Wf_hi[(size_t)NTOT * KTOT];
__device__ __nv_bfloat16 Wf_lo[(size_t)NTOT * KTOT];
__device__ float g_decays[(size_t)MTOT * DMODEL];
__device__ float g_inj[(size_t)MTOT * DMODEL];
__device__ float g_segA[BATCH * NSEG * DMODEL];
__device__ float g_segB[BATCH * NSEG * DMODEL];
__device__ float g_segInit[BATCH * NSEG * DMODEL];

// ---------------- PTX helpers ----------------
__device__ __forceinline__ uint32_t s2u(const void* p) {
    return (uint32_t)__cvta_generic_to_shared(p);
}

#define CPA16(s, g) asm volatile("cp.async.cg.shared.global [%0], [%1], 16;" :: "r"(s), "l"(g) : "memory")
#define CPA_COMMIT() asm volatile("cp.async.commit_group;" ::: "memory")
#define CPA_WAIT1()  asm volatile("cp.async.wait_group 1;" ::: "memory")
#define CPA_WAIT0()  asm volatile("cp.async.wait_group 0;" ::: "memory")

__device__ __forceinline__ void ldsm_x4(uint32_t addr, uint32_t& r0, uint32_t& r1,
                                        uint32_t& r2, uint32_t& r3) {
    asm volatile("ldmatrix.sync.aligned.m8n8.x4.shared.b16 {%0,%1,%2,%3}, [%4];"
                 : "=r"(r0), "=r"(r1), "=r"(r2), "=r"(r3) : "r"(addr));
}

__device__ __forceinline__ void mma16816(float* c, const uint32_t* a,
                                         uint32_t b0, uint32_t b1) {
    asm volatile(
        "mma.sync.aligned.m16n8k16.row.col.f32.bf16.bf16.f32 "
        "{%0,%1,%2,%3}, {%4,%5,%6,%7}, {%8,%9}, {%0,%1,%2,%3};"
        : "+f"(c[0]), "+f"(c[1]), "+f"(c[2]), "+f"(c[3])
        : "r"(a[0]), "r"(a[1]), "r"(a[2]), "r"(a[3]), "r"(b0), "r"(b1));
}

// ---------------- fp32 -> bf16 hi/lo split ----------------
__device__ __forceinline__ void split_bf(float x, unsigned short& h, unsigned short& l) {
    __nv_bfloat16 hb = __float2bfloat16_rn(x);
    float hf = __bfloat162float(hb);
    __nv_bfloat16 lb = __float2bfloat16_rn(x - hf);
    h = __bfloat16_as_ushort(hb);
    l = __bfloat16_as_ushort(lb);
}

__global__ __launch_bounds__(256)
void convert_x_kernel(const float* __restrict__ x) {
    size_t i = (size_t)blockIdx.x * 256 + threadIdx.x;      // float4 index
    float4 v = reinterpret_cast<const float4*>(x)[i];
    unsigned short h0, h1, h2, h3, l0, l1, l2, l3;
    split_bf(v.x, h0, l0); split_bf(v.y, h1, l1);
    split_bf(v.z, h2, l2); split_bf(v.w, h3, l3);
    uint2 uh, ul;
    uh.x = (uint32_t)h0 | ((uint32_t)h1 << 16);
    uh.y = (uint32_t)h2 | ((uint32_t)h3 << 16);
    ul.x = (uint32_t)l0 | ((uint32_t)l1 << 16);
    ul.y = (uint32_t)l2 | ((uint32_t)l3 << 16);
    reinterpret_cast<uint2*>(X_hi)[i] = uh;
    reinterpret_cast<uint2*>(X_lo)[i] = ul;
}

__global__ __launch_bounds__(256)
void convert_w_kernel(const float* __restrict__ Wd, const float* __restrict__ Wi) {
    size_t i = (size_t)blockIdx.x * 256 + threadIdx.x;      // float4 index, 524288
    int row = (int)(i >> 8);
    int c4  = (int)(i & 255);
    const float* src = (row < DMODEL) ? (Wd + (size_t)row * KTOT)
                                      : (Wi + (size_t)(row - DMODEL) * KTOT);
    float4 v = reinterpret_cast<const float4*>(src)[c4];
    unsigned short h0, h1, h2, h3, l0, l1, l2, l3;
    split_bf(v.x, h0, l0); split_bf(v.y, h1, l1);
    split_bf(v.z, h2, l2); split_bf(v.w, h3, l3);
    uint2 uh, ul;
    uh.x = (uint32_t)h0 | ((uint32_t)h1 << 16);
    uh.y = (uint32_t)h2 | ((uint32_t)h3 << 16);
    ul.x = (uint32_t)l0 | ((uint32_t)l1 << 16);
    ul.y = (uint32_t)l2 | ((uint32_t)l3 << 16);
    reinterpret_cast<uint2*>(Wf_hi)[i] = uh;
    reinterpret_cast<uint2*>(Wf_lo)[i] = ul;
}

// ---------------- GEMM: load one K-chunk into a stage ----------------
__device__ __forceinline__ void load_chunk(uint32_t smem_u, int c, int st,
                                           int m0, int n0, int tid) {
    const int k0 = c * K_CHUNK;
    const uint32_t base = smem_u + st * STAGE_BYTES;
    // A tiles: 128 rows x 4 16B chunks = 512 -> 2 iters of 256 threads
#pragma unroll
    for (int it = 0; it < 2; ++it) {
        int idx = it * 256 + tid;
        int row = idx >> 2;
        int kk  = (idx & 3) * 8;
        size_t gidx = (size_t)(m0 + row) * KTOT + k0 + kk;
        uint32_t so = (uint32_t)(row * PITCH + kk) * 2;
        CPA16(base + OFF_A_HI + so, X_hi + gidx);
        CPA16(base + OFF_A_LO + so, X_lo + gidx);
    }
    // B tiles: 128 n-rows x 4 chunks
#pragma unroll
    for (int it = 0; it < 2; ++it) {
        int idx = it * 256 + tid;
        int row = idx >> 2;
        int kk  = (idx & 3) * 8;
        size_t gidx = (size_t)(n0 + row) * KTOT + k0 + kk;
        uint32_t so = (uint32_t)(row * PITCH + kk) * 2;
        CPA16(base + OFF_B_HI + so, Wf_hi + gidx);
        CPA16(base + OFF_B_LO + so, Wf_lo + gidx);
    }
}

// ---------------- GEMM + gate epilogue (mma.sync bf16, 3-pass split) ----------------
__global__ __launch_bounds__(GTHREADS, 1)
void gemm_tc_kernel(const float* __restrict__ bd, const float* __restrict__ bi) {
    extern __shared__ char smem[];
    const uint32_t smem_u = s2u(smem);
    const int tid = threadIdx.x;
    const int wid = tid >> 5;
    const int lane = tid & 31;

    const int n0 = blockIdx.x * N_TILE;        // 0..1920
    const int m0 = blockIdx.y * M_TILE;
    const bool is_decay = (n0 < DMODEL);
    const int colbase = is_decay ? n0 : (n0 - DMODEL);
    const float* bv = is_decay ? bd : bi;

    const int warp_m = (wid & 3) * 32;         // 4 warps along M
    const int warp_n = (wid >> 2) * 64;        // 2 warps along N

    float acc[2][8][4];
#pragma unroll
    for (int mt = 0; mt < 2; ++mt)
#pragma unroll
        for (int nt = 0; nt < 8; ++nt)
#pragma unroll
            for (int q = 0; q < 4; ++q) acc[mt][nt][q] = 0.0f;

    // ldmatrix lane addressing (element offsets within a tile, pitch PITCH)
    const int a_r = lane & 15;                 // row within m16 tile
    const int a_c = (lane >> 4) * 8;           // k-offset 0/8
    const int b_quad = lane >> 3;              // 0..3
    const int b_r = lane & 7;
    const int b_row_off = ((b_quad >> 1) * 8) + b_r;   // row within n16 group
    const int b_k_off = (b_quad & 1) * 8;

    // prologue
    load_chunk(smem_u, 0, 0, m0, n0, tid); CPA_COMMIT();
    load_chunk(smem_u, 1, 1, m0, n0, tid); CPA_COMMIT();

    for (int c = 0; c < N_CHUNKS; ++c) {
        const int st = c & 1;
        if (c == N_CHUNKS - 1) { CPA_WAIT0(); } else { CPA_WAIT1(); }
        __syncthreads();

        const uint32_t base = smem_u + st * STAGE_BYTES;
#pragma unroll
        for (int kh = 0; kh < 2; ++kh) {
            const int kc = kh * 16;
            // A fragments for 2 m-tiles, hi & lo
            uint32_t ah[2][4], al[2][4];
#pragma unroll
            for (int mt = 0; mt < 2; ++mt) {
                uint32_t off = (uint32_t)((warp_m + mt * 16 + a_r) * PITCH + kc + a_c) * 2;
                ldsm_x4(base + OFF_A_HI + off, ah[mt][0], ah[mt][1], ah[mt][2], ah[mt][3]);
                ldsm_x4(base + OFF_A_LO + off, al[mt][0], al[mt][1], al[mt][2], al[mt][3]);
            }
#pragma unroll
            for (int ng = 0; ng < 4; ++ng) {   // n16 groups
                uint32_t off = (uint32_t)((warp_n + ng * 16 + b_row_off) * PITCH + kc + b_k_off) * 2;
                uint32_t bh0, bh1, bh2, bh3, bl0, bl1, bl2, bl3;
                ldsm_x4(base + OFF_B_HI + off, bh0, bh1, bh2, bh3);
                ldsm_x4(base + OFF_B_LO + off, bl0, bl1, bl2, bl3);
#pragma unroll
                for (int mt = 0; mt < 2; ++mt) {
                    // n-tile 2*ng : b frags {bh0,bh1} / {bl0,bl1}
                    mma16816(acc[mt][2 * ng + 0], ah[mt], bh0, bh1);
                    mma16816(acc[mt][2 * ng + 0], ah[mt], bl0, bl1);
                    mma16816(acc[mt][2 * ng + 0], al[mt], bh0, bh1);
                    // n-tile 2*ng+1 : {bh2,bh3} / {bl2,bl3}
                    mma16816(acc[mt][2 * ng + 1], ah[mt], bh2, bh3);
                    mma16816(acc[mt][2 * ng + 1], ah[mt], bl2, bl3);
                    mma16816(acc[mt][2 * ng + 1], al[mt], bh2, bh3);
                }
            }
        }
        __syncthreads();
        if (c < N_CHUNKS - 2) {
            load_chunk(smem_u, c + 2, st, m0, n0, tid);
            CPA_COMMIT();
        }
    }

    // ---- epilogue: bias (+sigmoid), direct float2 stores ----
    float* dst = is_decay ? g_decays : g_inj;
    float2 bias2[8];
#pragma unroll
    for (int nt = 0; nt < 8; ++nt) {
        int gcol = colbase + warp_n + nt * 8 + (lane & 3) * 2;
        bias2[nt] = *reinterpret_cast<const float2*>(bv + gcol);
    }
#pragma unroll
    for (int mt = 0; mt < 2; ++mt) {
        int row0 = m0 + warp_m + mt * 16 + (lane >> 2);
#pragma unroll
        for (int nt = 0; nt < 8; ++nt) {
            int gcol = colbase + warp_n + nt * 8 + (lane & 3) * 2;
            float v0 = acc[mt][nt][0] + bias2[nt].x;
            float v1 = acc[mt][nt][1] + bias2[nt].y;
            float v2 = acc[mt][nt][2] + bias2[nt].x;
            float v3 = acc[mt][nt][3] + bias2[nt].y;
            if (is_decay) {
                v0 = __fdividef(1.0f, 1.0f + __expf(-v0));
                v1 = __fdividef(1.0f, 1.0f + __expf(-v1));
                v2 = __fdividef(1.0f, 1.0f + __expf(-v2));
                v3 = __fdividef(1.0f, 1.0f + __expf(-v3));
            }
            *reinterpret_cast<float2*>(dst + (size_t)row0 * DMODEL + gcol) =
                make_float2(v0, v1);
            *reinterpret_cast<float2*>(dst + (size_t)(row0 + 8) * DMODEL + gcol) =
                make_float2(v2, v3);
        }
    }
}

// ---------------- segmented scan ----------------
__global__ __launch_bounds__(256)
void scan_pass1() {
    const int g = blockIdx.x * 256 + threadIdx.x;      // 0..131071
    const int e = g & (DMODEL - 1);
    const int bs = g >> 10;
    const int seg = bs & (NSEG - 1);
    const int b = bs >> 4;
    size_t p = ((size_t)b * SEQ + (size_t)seg * SEGLEN) * DMODEL + e;

    float s = 0.0f, A = 1.0f;
    for (int t = 0; t < SEGLEN; t += 8) {
        float d[8], v[8];
#pragma unroll
        for (int j = 0; j < 8; ++j) {
            d[j] = g_decays[p + (size_t)j * DMODEL];
            v[j] = g_inj[p + (size_t)j * DMODEL];
        }
#pragma unroll
        for (int j = 0; j < 8; ++j) {
            s = fmaf(d[j], s, v[j]);
            A *= d[j];
        }
        p += (size_t)8 * DMODEL;
    }
    g_segA[g] = A;
    g_segB[g] = s;
}

__global__ __launch_bounds__(256)
void scan_pass2() {
    const int g = blockIdx.x * 256 + threadIdx.x;      // 0..8191
    const int e = g & (DMODEL - 1);
    const int b = g >> 10;
    float s = 0.0f;
#pragma unroll
    for (int seg = 0; seg < NSEG; ++seg) {
        int idx = ((b * NSEG + seg) << 10) | e;
        g_segInit[idx] = s;
        s = fmaf(g_segA[idx], s, g_segB[idx]);
    }
}

__global__ __launch_bounds__(256)
void scan_pass3(float* __restrict__ out) {
    const int g = blockIdx.x * 256 + threadIdx.x;
    const int e = g & (DMODEL - 1);
    const int bs = g >> 10;
    const int seg = bs & (NSEG - 1);
    const int b = bs >> 4;
    size_t p = ((size_t)b * SEQ + (size_t)seg * SEGLEN) * DMODEL + e;

    float s = g_segInit[g];
    for (int t = 0; t < SEGLEN; t += 8) {
        float d[8], v[8];
#pragma unroll
        for (int j = 0; j < 8; ++j) {
            d[j] = g_decays[p + (size_t)j * DMODEL];
            v[j] = g_inj[p + (size_t)j * DMODEL];
        }
#pragma unroll
        for (int j = 0; j < 8; ++j) {
            s = fmaf(d[j], s, v[j]);
            out[p + (size_t)j * DMODEL] = s;
        }
        p += (size_t)8 * DMODEL;
    }
}

// ---------------- launch ----------------
extern "C" void kernel_launch(void* const* d_in, const int* in_sizes, int n_in,
                              void* d_out, int out_size) {
    const float* x_seq   = (const float*)d_in[0];
    const float* W_decay = (const float*)d_in[1];
    const float* b_decay = (const float*)d_in[2];
    const float* W_input = (const float*)d_in[3];
    const float* b_input = (const float*)d_in[4];
    float* out = (float*)d_out;

    static bool attr_set = false;
    if (!attr_set) {
        cudaFuncSetAttribute(gemm_tc_kernel,
                             cudaFuncAttributeMaxDynamicSharedMemorySize, SMEM_TOTAL);
        attr_set = true;
    }

    convert_x_kernel<<<(MTOT * KTOT / 4) / 256, 256>>>(x_seq);
    convert_w_kernel<<<(NTOT * KTOT / 4) / 256, 256>>>(W_decay, W_input);

    dim3 grid(NTOT / N_TILE, MTOT / M_TILE);   // (16, 256): n fastest -> A reuse in L2
    gemm_tc_kernel<<<grid, GTHREADS, SMEM_TOTAL>>>(b_decay, b_input);

    scan_pass1<<<(BATCH * NSEG * DMODEL) / 256, 256>>>();
    scan_pass2<<<(BATCH * DMODEL) / 256, 256>>>();
    scan_pass3<<<(BATCH * NSEG * DMODEL) / 256, 256>>>(out);
}

// round 5
// speedup vs baseline: 2.9884x; 1.2182x over previous
#include <cuda_runtime.h>
#include <cuda_bf16.h>
#include <cstdint>

// ---------------- problem constants ----------------
#define BATCH   8
#define SEQ     4096
#define DMODEL  1024
#define MTOT    (BATCH * SEQ)      // 32768
#define KTOT    DMODEL             // 1024
#define NTOT    (2 * DMODEL)       // 2048 fused (decay | input)

// ---------------- GEMM tiling ----------------
#define M_TILE   128
#define N_TILE   128
#define K_CHUNK  32
#define N_CHUNKS (KTOT / K_CHUNK)   // 32
#define GTHREADS 512
#define NSTAGE   4

// smem: padded pitch 40 bf16 (80 B) -> conflict-free ldmatrix
#define PITCH 40
#define TILE_BYTES (128 * PITCH * 2)      // 10240
#define OFF_A_HI 0
#define OFF_A_LO (1 * TILE_BYTES)
#define OFF_B_HI (2 * TILE_BYTES)
#define OFF_B_LO (3 * TILE_BYTES)
#define STAGE_BYTES (4 * TILE_BYTES)      // 40960
#define SMEM_TOTAL  (NSTAGE * STAGE_BYTES) // 163840

// ---------------- scan segmentation ----------------
#define NSEG   16
#define SEGLEN (SEQ / NSEG)         // 256

// ---------------- device scratch ----------------
__device__ __nv_bfloat16 X_hi[(size_t)MTOT * KTOT];
__device__ __nv_bfloat16 X_lo[(size_t)MTOT * KTOT];
__device__ __nv_bfloat16 Wf_hi[(size_t)NTOT * KTOT];
__device__ __nv_bfloat16 Wf_lo[(size_t)NTOT * KTOT];
__device__ float g_decays[(size_t)MTOT * DMODEL];
__device__ float g_inj[(size_t)MTOT * DMODEL];
__device__ float g_segA[BATCH * NSEG * DMODEL];
__device__ float g_segB[BATCH * NSEG * DMODEL];
__device__ float g_segInit[BATCH * NSEG * DMODEL];

// ---------------- PTX helpers ----------------
__device__ __forceinline__ uint32_t s2u(const void* p) {
    return (uint32_t)__cvta_generic_to_shared(p);
}

#define CPA16(s, g) asm volatile("cp.async.cg.shared.global [%0], [%1], 16;" :: "r"(s), "l"(g) : "memory")
#define CPA_COMMIT() asm volatile("cp.async.commit_group;" ::: "memory")
#define CPA_WAIT2()  asm volatile("cp.async.wait_group 2;" ::: "memory")
#define CPA_WAIT1()  asm volatile("cp.async.wait_group 1;" ::: "memory")
#define CPA_WAIT0()  asm volatile("cp.async.wait_group 0;" ::: "memory")

__device__ __forceinline__ void ldsm_x4(uint32_t addr, uint32_t& r0, uint32_t& r1,
                                        uint32_t& r2, uint32_t& r3) {
    asm volatile("ldmatrix.sync.aligned.m8n8.x4.shared.b16 {%0,%1,%2,%3}, [%4];"
                 : "=r"(r0), "=r"(r1), "=r"(r2), "=r"(r3) : "r"(addr));
}

__device__ __forceinline__ void mma16816(float* c, const uint32_t* a,
                                         uint32_t b0, uint32_t b1) {
    asm volatile(
        "mma.sync.aligned.m16n8k16.row.col.f32.bf16.bf16.f32 "
        "{%0,%1,%2,%3}, {%4,%5,%6,%7}, {%8,%9}, {%0,%1,%2,%3};"
        : "+f"(c[0]), "+f"(c[1]), "+f"(c[2]), "+f"(c[3])
        : "r"(a[0]), "r"(a[1]), "r"(a[2]), "r"(a[3]), "r"(b0), "r"(b1));
}

// ---------------- fp32 -> bf16 hi/lo split ----------------
__device__ __forceinline__ void split_bf(float x, unsigned short& h, unsigned short& l) {
    __nv_bfloat16 hb = __float2bfloat16_rn(x);
    float hf = __bfloat162float(hb);
    __nv_bfloat16 lb = __float2bfloat16_rn(x - hf);
    h = __bfloat16_as_ushort(hb);
    l = __bfloat16_as_ushort(lb);
}

__global__ __launch_bounds__(256)
void convert_x_kernel(const float* __restrict__ x) {
    size_t i = (size_t)blockIdx.x * 256 + threadIdx.x;      // float4 index
    float4 v = reinterpret_cast<const float4*>(x)[i];
    unsigned short h0, h1, h2, h3, l0, l1, l2, l3;
    split_bf(v.x, h0, l0); split_bf(v.y, h1, l1);
    split_bf(v.z, h2, l2); split_bf(v.w, h3, l3);
    uint2 uh, ul;
    uh.x = (uint32_t)h0 | ((uint32_t)h1 << 16);
    uh.y = (uint32_t)h2 | ((uint32_t)h3 << 16);
    ul.x = (uint32_t)l0 | ((uint32_t)l1 << 16);
    ul.y = (uint32_t)l2 | ((uint32_t)l3 << 16);
    reinterpret_cast<uint2*>(X_hi)[i] = uh;
    reinterpret_cast<uint2*>(X_lo)[i] = ul;
}

__global__ __launch_bounds__(256)
void convert_w_kernel(const float* __restrict__ Wd, const float* __restrict__ Wi) {
    size_t i = (size_t)blockIdx.x * 256 + threadIdx.x;      // float4 index, 524288
    int row = (int)(i >> 8);
    int c4  = (int)(i & 255);
    const float* src = (row < DMODEL) ? (Wd + (size_t)row * KTOT)
                                      : (Wi + (size_t)(row - DMODEL) * KTOT);
    float4 v = reinterpret_cast<const float4*>(src)[c4];
    unsigned short h0, h1, h2, h3, l0, l1, l2, l3;
    split_bf(v.x, h0, l0); split_bf(v.y, h1, l1);
    split_bf(v.z, h2, l2); split_bf(v.w, h3, l3);
    uint2 uh, ul;
    uh.x = (uint32_t)h0 | ((uint32_t)h1 << 16);
    uh.y = (uint32_t)h2 | ((uint32_t)h3 << 16);
    ul.x = (uint32_t)l0 | ((uint32_t)l1 << 16);
    ul.y = (uint32_t)l2 | ((uint32_t)l3 << 16);
    reinterpret_cast<uint2*>(Wf_hi)[i] = uh;
    reinterpret_cast<uint2*>(Wf_lo)[i] = ul;
}

// ---------------- GEMM: load one K-chunk into a stage ----------------
// 512 threads: A = 128 rows x 4 16B-chunks = 512 transfers (1 per thread), same for B.
__device__ __forceinline__ void load_chunk(uint32_t smem_u, int c, int st,
                                           int m0, int n0, int tid) {
    const int k0 = c * K_CHUNK;
    const uint32_t base = smem_u + st * STAGE_BYTES;
    const int row = tid >> 2;
    const int kk  = (tid & 3) * 8;
    const uint32_t so = (uint32_t)(row * PITCH + kk) * 2;
    {
        size_t gidx = (size_t)(m0 + row) * KTOT + k0 + kk;
        CPA16(base + OFF_A_HI + so, X_hi + gidx);
        CPA16(base + OFF_A_LO + so, X_lo + gidx);
    }
    {
        size_t gidx = (size_t)(n0 + row) * KTOT + k0 + kk;
        CPA16(base + OFF_B_HI + so, Wf_hi + gidx);
        CPA16(base + OFF_B_LO + so, Wf_lo + gidx);
    }
}

// ---------------- GEMM + gate epilogue (mma.sync bf16, 3-pass split) ----------------
// 16 warps in 4x4 layout; warp tile 32x32.
__global__ __launch_bounds__(GTHREADS, 1)
void gemm_tc_kernel(const float* __restrict__ bd, const float* __restrict__ bi) {
    extern __shared__ char smem[];
    const uint32_t smem_u = s2u(smem);
    const int tid = threadIdx.x;
    const int wid = tid >> 5;
    const int lane = tid & 31;

    const int n0 = blockIdx.x * N_TILE;        // 0..1920
    const int m0 = blockIdx.y * M_TILE;
    const bool is_decay = (n0 < DMODEL);
    const int colbase = is_decay ? n0 : (n0 - DMODEL);
    const float* bv = is_decay ? bd : bi;

    const int warp_m = (wid & 3) * 32;         // 4 warps along M
    const int warp_n = (wid >> 2) * 32;        // 4 warps along N

    float acc[2][4][4];
#pragma unroll
    for (int mt = 0; mt < 2; ++mt)
#pragma unroll
        for (int nt = 0; nt < 4; ++nt)
#pragma unroll
            for (int q = 0; q < 4; ++q) acc[mt][nt][q] = 0.0f;

    // ldmatrix lane addressing
    const int a_r = lane & 15;
    const int a_c = (lane >> 4) * 8;
    const int b_quad = lane >> 3;
    const int b_r = lane & 7;
    const int b_row_off = ((b_quad >> 1) * 8) + b_r;
    const int b_k_off = (b_quad & 1) * 8;

    // prologue: fill 3 of 4 stages
    load_chunk(smem_u, 0, 0, m0, n0, tid); CPA_COMMIT();
    load_chunk(smem_u, 1, 1, m0, n0, tid); CPA_COMMIT();
    load_chunk(smem_u, 2, 2, m0, n0, tid); CPA_COMMIT();

    for (int c = 0; c < N_CHUNKS; ++c) {
        if (c <= N_CHUNKS - 3)      { CPA_WAIT2(); }
        else if (c == N_CHUNKS - 2) { CPA_WAIT1(); }
        else                        { CPA_WAIT0(); }
        __syncthreads();

        const uint32_t base = smem_u + (c & (NSTAGE - 1)) * STAGE_BYTES;
#pragma unroll
        for (int kh = 0; kh < 2; ++kh) {
            const int kc = kh * 16;
            uint32_t ah[2][4], al[2][4];
#pragma unroll
            for (int mt = 0; mt < 2; ++mt) {
                uint32_t off = (uint32_t)((warp_m + mt * 16 + a_r) * PITCH + kc + a_c) * 2;
                ldsm_x4(base + OFF_A_HI + off, ah[mt][0], ah[mt][1], ah[mt][2], ah[mt][3]);
                ldsm_x4(base + OFF_A_LO + off, al[mt][0], al[mt][1], al[mt][2], al[mt][3]);
            }
#pragma unroll
            for (int ng = 0; ng < 2; ++ng) {   // n16 groups
                uint32_t off = (uint32_t)((warp_n + ng * 16 + b_row_off) * PITCH + kc + b_k_off) * 2;
                uint32_t bh0, bh1, bh2, bh3, bl0, bl1, bl2, bl3;
                ldsm_x4(base + OFF_B_HI + off, bh0, bh1, bh2, bh3);
                ldsm_x4(base + OFF_B_LO + off, bl0, bl1, bl2, bl3);
#pragma unroll
                for (int mt = 0; mt < 2; ++mt) {
                    mma16816(acc[mt][2 * ng + 0], ah[mt], bh0, bh1);
                    mma16816(acc[mt][2 * ng + 0], ah[mt], bl0, bl1);
                    mma16816(acc[mt][2 * ng + 0], al[mt], bh0, bh1);
                    mma16816(acc[mt][2 * ng + 1], ah[mt], bh2, bh3);
                    mma16816(acc[mt][2 * ng + 1], ah[mt], bl2, bl3);
                    mma16816(acc[mt][2 * ng + 1], al[mt], bh2, bh3);
                }
            }
        }
        if (c + 3 < N_CHUNKS) {
            load_chunk(smem_u, c + 3, (c + 3) & (NSTAGE - 1), m0, n0, tid);
            CPA_COMMIT();
        }
    }

    // ---- epilogue: bias (+sigmoid), direct float2 stores ----
    float* dst = is_decay ? g_decays : g_inj;
    float2 bias2[4];
#pragma unroll
    for (int nt = 0; nt < 4; ++nt) {
        int gcol = colbase + warp_n + nt * 8 + (lane & 3) * 2;
        bias2[nt] = *reinterpret_cast<const float2*>(bv + gcol);
    }
#pragma unroll
    for (int mt = 0; mt < 2; ++mt) {
        int row0 = m0 + warp_m + mt * 16 + (lane >> 2);
#pragma unroll
        for (int nt = 0; nt < 4; ++nt) {
            int gcol = colbase + warp_n + nt * 8 + (lane & 3) * 2;
            float v0 = acc[mt][nt][0] + bias2[nt].x;
            float v1 = acc[mt][nt][1] + bias2[nt].y;
            float v2 = acc[mt][nt][2] + bias2[nt].x;
            float v3 = acc[mt][nt][3] + bias2[nt].y;
            if (is_decay) {
                v0 = __fdividef(1.0f, 1.0f + __expf(-v0));
                v1 = __fdividef(1.0f, 1.0f + __expf(-v1));
                v2 = __fdividef(1.0f, 1.0f + __expf(-v2));
                v3 = __fdividef(1.0f, 1.0f + __expf(-v3));
            }
            *reinterpret_cast<float2*>(dst + (size_t)row0 * DMODEL + gcol) =
                make_float2(v0, v1);
            *reinterpret_cast<float2*>(dst + (size_t)(row0 + 8) * DMODEL + gcol) =
                make_float2(v2, v3);
        }
    }
}

// ---------------- segmented scan ----------------
__global__ __launch_bounds__(256)
void scan_pass1() {
    const int g = blockIdx.x * 256 + threadIdx.x;      // 0..131071
    const int e = g & (DMODEL - 1);
    const int bs = g >> 10;
    const int seg = bs & (NSEG - 1);
    const int b = bs >> 4;
    size_t p = ((size_t)b * SEQ + (size_t)seg * SEGLEN) * DMODEL + e;

    float s = 0.0f, A = 1.0f;
    for (int t = 0; t < SEGLEN; t += 8) {
        float d[8], v[8];
#pragma unroll
        for (int j = 0; j < 8; ++j) {
            d[j] = g_decays[p + (size_t)j * DMODEL];
            v[j] = g_inj[p + (size_t)j * DMODEL];
        }
#pragma unroll
        for (int j = 0; j < 8; ++j) {
            s = fmaf(d[j], s, v[j]);
            A *= d[j];
        }
        p += (size_t)8 * DMODEL;
    }
    g_segA[g] = A;
    g_segB[g] = s;
}

__global__ __launch_bounds__(256)
void scan_pass2() {
    const int g = blockIdx.x * 256 + threadIdx.x;      // 0..8191
    const int e = g & (DMODEL - 1);
    const int b = g >> 10;
    float s = 0.0f;
#pragma unroll
    for (int seg = 0; seg < NSEG; ++seg) {
        int idx = ((b * NSEG + seg) << 10) | e;
        g_segInit[idx] = s;
        s = fmaf(g_segA[idx], s, g_segB[idx]);
    }
}

__global__ __launch_bounds__(256)
void scan_pass3(float* __restrict__ out) {
    const int g = blockIdx.x * 256 + threadIdx.x;
    const int e = g & (DMODEL - 1);
    const int bs = g >> 10;
    const int seg = bs & (NSEG - 1);
    const int b = bs >> 4;
    size_t p = ((size_t)b * SEQ + (size_t)seg * SEGLEN) * DMODEL + e;

    float s = g_segInit[g];
    for (int t = 0; t < SEGLEN; t += 8) {
        float d[8], v[8];
#pragma unroll
        for (int j = 0; j < 8; ++j) {
            d[j] = g_decays[p + (size_t)j * DMODEL];
            v[j] = g_inj[p + (size_t)j * DMODEL];
        }
#pragma unroll
        for (int j = 0; j < 8; ++j) {
            s = fmaf(d[j], s, v[j]);
            out[p + (size_t)j * DMODEL] = s;
        }
        p += (size_t)8 * DMODEL;
    }
}

// ---------------- launch ----------------
extern "C" void kernel_launch(void* const* d_in, const int* in_sizes, int n_in,
                              void* d_out, int out_size) {
    const float* x_seq   = (const float*)d_in[0];
    const float* W_decay = (const float*)d_in[1];
    const float* b_decay = (const float*)d_in[2];
    const float* W_input = (const float*)d_in[3];
    const float* b_input = (const float*)d_in[4];
    float* out = (float*)d_out;

    static bool attr_set = false;
    if (!attr_set) {
        cudaFuncSetAttribute(gemm_tc_kernel,
                             cudaFuncAttributeMaxDynamicSharedMemorySize, SMEM_TOTAL);
        attr_set = true;
    }

    convert_x_kernel<<<(MTOT * KTOT / 4) / 256, 256>>>(x_seq);
    convert_w_kernel<<<(NTOT * KTOT / 4) / 256, 256>>>(W_decay, W_input);

    dim3 grid(NTOT / N_TILE, MTOT / M_TILE);   // (16, 256): n fastest -> A reuse in L2
    gemm_tc_kernel<<<grid, GTHREADS, SMEM_TOTAL>>>(b_decay, b_input);

    scan_pass1<<<(BATCH * NSEG * DMODEL) / 256, 256>>>();
    scan_pass2<<<(BATCH * DMODEL) / 256, 256>>>();
    scan_pass3<<<(BATCH * NSEG * DMODEL) / 256, 256>>>(out);
}